// round 8
// baseline (speedup 1.0000x reference)
#include <cuda_runtime.h>

// Warp1DOp, direct gather, 4 px/thread.
// Both bilinear taps (c0, c0+1) fetched with ONE aligned LDG.128 from
// (c0 & ~3); scalar fallback LDG only when c0 % 4 == 3. This cuts L1tex
// gather wavefronts ~1.6x vs two scalar taps. Zeros padding via predication.

#define N_ 4
#define C_ 32
#define H_ 384
#define W_ 1280
#define HW_ (H_ * W_)
#define CHW_ (C_ * HW_)
#define NHW_ (N_ * H_ * W_)
#define W4_ (W_ / 4)
#define NHW4_ (NHW_ / 4)

__device__ __forceinline__ float sel4(float4 f, int k) {
    float r = f.w;
    r = (k == 2) ? f.z : r;
    r = (k == 1) ? f.y : r;
    r = (k == 0) ? f.x : r;
    return r;
}

__global__ __launch_bounds__(256) void warp1d_kernel(
    const float* __restrict__ img,
    const float* __restrict__ disp,
    float* __restrict__ out)
{
    int t = blockIdx.x * blockDim.x + threadIdx.x;   // over N*H*W/4
    if (t >= NHW4_) return;

    int w4 = t % W4_;
    int nh = t / W4_;           // n*H + h
    int n  = nh / H_;
    int h  = nh % H_;
    int w  = w4 * 4;

    float4 d4 = reinterpret_cast<const float4*>(disp)[t];
    float dv[4] = {d4.x, d4.y, d4.z, d4.w};

    int   c0[4], c1[4], ab[4];   // taps and aligned float4 base
    float dx[4], mdx[4];
    bool  v0[4], v1[4];

#pragma unroll
    for (int i = 0; i < 4; ++i) {
        float x = (float)(w + i) - dv[i];
        x = fminf(fmaxf(x, -1.0f), (float)W_) + 1.0f;   // [0, W+1] padded coord
        float xf = floorf(x);
        int   p0 = (int)xf;
        float f  = x - xf;
        int   p1 = p0 + (f > 0.0f ? 1 : 0);             // == ceil(x)
        c0[i] = p0 - 1;                                  // real img column
        c1[i] = p1 - 1;
        v0[i] = ((unsigned)c0[i] < (unsigned)W_);
        v1[i] = ((unsigned)c1[i] < (unsigned)W_);
        int a = c0[i] & ~3;                              // aligned base
        a = a < 0 ? 0 : a;
        a = a > (W_ - 4) ? (W_ - 4) : a;
        ab[i]  = a;
        dx[i]  = f;
        mdx[i] = 1.0f - f;
    }

    size_t base = (size_t)n * CHW_ + (size_t)h * W_;
    const float* __restrict__ irow = img + base;
    float* __restrict__ orow = out + base + w;

#pragma unroll 4
    for (int c = 0; c < C_; ++c) {
        const float* r = irow + (size_t)c * HW_;
        float4 o;
        float* op = &o.x;
#pragma unroll
        for (int i = 0; i < 4; ++i) {
            float4 f4 = __ldg(reinterpret_cast<const float4*>(r + ab[i]));
            float t0 = sel4(f4, c0[i] - ab[i]);
            t0 = v0[i] ? t0 : 0.0f;
            float t1;
            int o1 = c1[i] - ab[i];
            if (o1 < 4) {
                t1 = sel4(f4, o1);
                t1 = v1[i] ? t1 : 0.0f;
            } else {
                t1 = v1[i] ? __ldg(r + c1[i]) : 0.0f;    // predicated, no OOB
            }
            op[i] = mdx[i] * t0 + dx[i] * t1;
        }
        *reinterpret_cast<float4*>(orow + (size_t)c * HW_) = o;
    }
}

extern "C" void kernel_launch(void* const* d_in, const int* in_sizes, int n_in,
                              void* d_out, int out_size)
{
    const float* img  = (const float*)d_in[0];
    const float* disp = (const float*)d_in[1];
    float* out = (float*)d_out;

    const int threads = 256;
    const int blocks  = (NHW4_ + threads - 1) / threads;
    warp1d_kernel<<<blocks, threads>>>(img, disp, out);
}

// round 9
// speedup vs baseline: 2.7833x; 2.7833x over previous
#include <cuda_runtime.h>

// Warp1DOp, direct gather, 4 px/thread (best-known structure = R4),
// plus cache-policy hints:
//   disp: __ldcs  (streaming, zero reuse)
//   img : __ldg   (default caching -- gather windows overlap across warps)
//   out : __stcs  (evict-first; drain dirty lines early, smooth DRAM writes)

#define N_ 4
#define C_ 32
#define H_ 384
#define W_ 1280
#define HW_ (H_ * W_)
#define CHW_ (C_ * HW_)
#define NHW_ (N_ * H_ * W_)
#define W4_ (W_ / 4)
#define NHW4_ (NHW_ / 4)

__global__ __launch_bounds__(256) void warp1d_kernel(
    const float* __restrict__ img,
    const float* __restrict__ disp,
    float* __restrict__ out)
{
    int t = blockIdx.x * blockDim.x + threadIdx.x;   // over N*H*W/4
    if (t >= NHW4_) return;

    int w4 = t % W4_;
    int nh = t / W4_;           // n*H + h
    int n  = nh / H_;
    int h  = nh % H_;
    int w  = w4 * 4;

    float4 d4 = __ldcs(reinterpret_cast<const float4*>(disp) + t);
    float dv[4] = {d4.x, d4.y, d4.z, d4.w};

    int   c0[4], c1[4];
    float dx[4], mdx[4];
    bool  v0[4], v1[4];

#pragma unroll
    for (int i = 0; i < 4; ++i) {
        float x = (float)(w + i) - dv[i];
        x = fminf(fmaxf(x, -1.0f), (float)W_) + 1.0f;   // [0, W+1] padded coord
        float xf = floorf(x);
        int   p0 = (int)xf;
        float f  = x - xf;
        int   p1 = p0 + (f > 0.0f ? 1 : 0);             // == ceil(x)
        c0[i] = p0 - 1;                                  // real img column
        c1[i] = p1 - 1;
        v0[i] = ((unsigned)c0[i] < (unsigned)W_);
        v1[i] = ((unsigned)c1[i] < (unsigned)W_);
        dx[i]  = f;
        mdx[i] = 1.0f - f;
    }

    size_t base = (size_t)n * CHW_ + (size_t)h * W_;
    const float* __restrict__ irow = img + base;
    float* __restrict__ orow = out + base + w;

#pragma unroll 4
    for (int c = 0; c < C_; ++c) {
        const float* r = irow + (size_t)c * HW_;
        float a0 = v0[0] ? __ldg(r + c0[0]) : 0.0f;
        float b0 = v1[0] ? __ldg(r + c1[0]) : 0.0f;
        float a1 = v0[1] ? __ldg(r + c0[1]) : 0.0f;
        float b1 = v1[1] ? __ldg(r + c1[1]) : 0.0f;
        float a2 = v0[2] ? __ldg(r + c0[2]) : 0.0f;
        float b2 = v1[2] ? __ldg(r + c1[2]) : 0.0f;
        float a3 = v0[3] ? __ldg(r + c0[3]) : 0.0f;
        float b3 = v1[3] ? __ldg(r + c1[3]) : 0.0f;

        float4 o;
        o.x = mdx[0] * a0 + dx[0] * b0;
        o.y = mdx[1] * a1 + dx[1] * b1;
        o.z = mdx[2] * a2 + dx[2] * b2;
        o.w = mdx[3] * a3 + dx[3] * b3;
        __stcs(reinterpret_cast<float4*>(orow + (size_t)c * HW_), o);
    }
}

extern "C" void kernel_launch(void* const* d_in, const int* in_sizes, int n_in,
                              void* d_out, int out_size)
{
    const float* img  = (const float*)d_in[0];
    const float* disp = (const float*)d_in[1];
    float* out = (float*)d_out;

    const int threads = 256;
    const int blocks  = (NHW4_ + threads - 1) / threads;
    warp1d_kernel<<<blocks, threads>>>(img, disp, out);
}